// round 8
// baseline (speedup 1.0000x reference)
#include <cuda_runtime.h>
#include <cuda_fp16.h>
#include <cstdint>
#include <cstddef>

#define DEV __device__ __forceinline__

static constexpr int Bn = 8192;   // batch rows
static constexpr int Dd = 2048;   // model dim (K of GEMMs, N of V GEMM)
static constexpr int Ff = 1024;   // feature dim (N of Q/K GEMMs)

// ---------------- scratch (device globals: allocation-free) ----------------
__device__ __half g_Qh [(size_t)Bn * Dd];   // 32 MB
__device__ __half g_Kh [(size_t)Bn * Dd];   // 32 MB
__device__ __half g_Vh [(size_t)Bn * Dd];   // 32 MB
__device__ __half g_WqT[(size_t)Ff * Dd];   // [F][D] 4 MB
__device__ __half g_WkT[(size_t)Ff * Dd];   // [F][D] 4 MB
__device__ __half g_WvT[(size_t)Dd * Dd];   // [D][D] 8 MB
__device__ float g_sQ[Bn];
__device__ float g_sK[Bn];
__device__ float g_qk[Bn];

// ---------------- helpers ----------------
DEV uint32_t smem_u32(const void* p) {
  uint32_t a;
  asm("{ .reg .u64 t; cvta.to.shared.u64 t, %1; cvt.u32.u64 %0, t; }" : "=r"(a) : "l"(p));
  return a;
}
DEV void cp16(uint32_t dst, const void* src) {
  asm volatile("cp.async.cg.shared.global [%0], [%1], 16;" :: "r"(dst), "l"(src));
}
DEV void cp_commit() { asm volatile("cp.async.commit_group;" ::: "memory"); }
DEV void cp_wait1()  { asm volatile("cp.async.wait_group 1;" ::: "memory"); }

// mma m16n8k16 fp16 (fp32 acc): A row-major (4 regs = 8 halves), B col-major (2 regs)
DEV void mma16(float c[4], const uint32_t a[4], const uint32_t b[2]) {
  asm volatile(
    "mma.sync.aligned.m16n8k16.row.col.f32.f16.f16.f32 "
    "{%0,%1,%2,%3}, {%4,%5,%6,%7}, {%8,%9}, {%0,%1,%2,%3};"
    : "+f"(c[0]), "+f"(c[1]), "+f"(c[2]), "+f"(c[3])
    : "r"(a[0]), "r"(a[1]), "r"(a[2]), "r"(a[3]), "r"(b[0]), "r"(b[1]));
}

DEV float elu_f(float x) { return x > 0.f ? x : expm1f(x); }
DEV uint32_t ldh2(const __half* p) { return *reinterpret_cast<const uint32_t*>(p); }
DEV uint32_t f2h2(float x, float y) {
  __half2 h = __floats2half2_rn(x, y);
  return *reinterpret_cast<uint32_t*>(&h);
}

// Smem rows: 64 k-halves (128 B data) padded to 72 halves (144 B = 9*16 B).
// word bank = (4r + tig + 4c) mod 32 -> conflict-free for A- and B-frag loads.
static constexpr int ROWH = 72;                    // halves per padded row
static constexpr int ROWB = 144;                   // bytes per padded row

// ---------------- prep kernels ----------------
__global__ void f2h_all_kernel(const float* __restrict__ Q,
                               const float* __restrict__ K,
                               const float* __restrict__ V) {
  const int bi = blockIdx.x;            // 0..24575 (8192 blocks per tensor)
  const int which = bi >> 13;
  const int blk = bi & 8191;
  const float* src = (which == 0) ? Q : (which == 1) ? K : V;
  __half* dst = (which == 0) ? g_Qh : (which == 1) ? g_Kh : g_Vh;
  const size_t base = ((size_t)blk * 256 + threadIdx.x) * 8;
  float4 a = *reinterpret_cast<const float4*>(src + base);
  float4 b = *reinterpret_cast<const float4*>(src + base + 4);
  uint4 o;
  o.x = f2h2(a.x, a.y); o.y = f2h2(a.z, a.w);
  o.z = f2h2(b.x, b.y); o.w = f2h2(b.z, b.w);
  *reinterpret_cast<uint4*>(dst + base) = o;
}

__global__ void transpose_all_kernel(const float* __restrict__ Wq,
                                     const float* __restrict__ Wk,
                                     const float* __restrict__ Wv) {
  __shared__ float tile[32][33];
  const int z = blockIdx.z;
  if (z < 2 && blockIdx.x >= Ff / 32) return;
  const float* src = (z == 0) ? Wq : (z == 1) ? Wk : Wv;
  __half* dst = (z == 0) ? g_WqT : (z == 1) ? g_WkT : g_WvT;
  const int C = (z == 2) ? Dd : Ff;
  const int c0 = blockIdx.x * 32, r0 = blockIdx.y * 32;
  const int tx = threadIdx.x, ty = threadIdx.y;
  #pragma unroll
  for (int i = 0; i < 32; i += 8)
    tile[ty + i][tx] = src[(size_t)(r0 + ty + i) * C + (c0 + tx)];
  __syncthreads();
  #pragma unroll
  for (int i = 0; i < 32; i += 8)
    dst[(size_t)(c0 + ty + i) * Dd + (r0 + tx)] = __float2half_rn(tile[tx][ty + i]);
}

__global__ void zero_kernel() {
  int i = blockIdx.x * blockDim.x + threadIdx.x;
  if (i < Bn) { g_sQ[i] = 0.f; g_sK[i] = 0.f; g_qk[i] = 0.f; }
}

// ---------------- fused Q/K feature kernel ----------------
// CTA 128 rows x 128 feature cols, BOTH gemms; 8 warps (wm 2 x wn 4),
// warp tile 64x32 per gemm (acc 128 regs). K-chunk 64, 2-stage, 1 CTA/SM.
// Stage: A region 256 rows (AQ 128 | AK 128) = 36864 B,
//        B region 256 rows (BQ 128 | BK 128) = 36864 B.  Stage = 73728 B.
static constexpr int QK_STAGE = 512 * ROWB;               // 73728
static constexpr int QK_SMEM  = 2 * QK_STAGE;             // 147456

__global__ void __launch_bounds__(256, 1)
gemm_qk_kernel(const float* __restrict__ bq, const float* __restrict__ bk)
{
  extern __shared__ __align__(128) char smem[];
  __half* fs = reinterpret_cast<__half*>(smem);
  const uint32_t sb = smem_u32(smem);
  const int tid = threadIdx.x;
  const int wid = tid >> 5, lane = tid & 31;
  const int g = lane >> 2, tig = lane & 3;
  const int wm = wid >> 2, wn = wid & 3;
  const int m0 = blockIdx.y * 128;
  const int n0 = blockIdx.x * 128;

  auto load_stage = [&](int it, int s) {
    const int k0 = it * 64;                 // halves
    const uint32_t base = sb + (uint32_t)s * QK_STAGE;
    // A region: 2048 16B chunks (rows 0-127 Q, 128-255 K); 8 per thread.
    #pragma unroll
    for (int i = 0; i < 8; ++i) {
      int ch = tid + i * 256;               // i<4 -> Q, i>=4 -> K (uniform)
      int r = ch >> 3, c = ch & 7;
      uint32_t off = (uint32_t)(r * ROWB + c * 16);
      const __half* src = (i < 4) ? (g_Qh + (size_t)(m0 + r) * Dd)
                                  : (g_Kh + (size_t)(m0 + r - 128) * Dd);
      cp16(base + off, src + k0 + c * 8);
    }
    // B region: 2048 chunks (rows 0-127 Wq, 128-255 Wk); 8 per thread.
    #pragma unroll
    for (int i = 0; i < 8; ++i) {
      int ch = tid + i * 256;
      int r = ch >> 3, c = ch & 7;
      uint32_t off = (uint32_t)(256 * ROWB + r * ROWB + c * 16);
      const __half* src = (i < 4) ? (g_WqT + (size_t)(n0 + r) * Dd)
                                  : (g_WkT + (size_t)(n0 + r - 128) * Dd);
      cp16(base + off, src + k0 + c * 8);
    }
    cp_commit();
  };

  float cQ[4][4][4], cK[4][4][4];
  #pragma unroll
  for (int i = 0; i < 4; ++i)
    #pragma unroll
    for (int j = 0; j < 4; ++j)
      #pragma unroll
      for (int t = 0; t < 4; ++t) { cQ[i][j][t] = 0.f; cK[i][j][t] = 0.f; }

  load_stage(0, 0);

  const int NIT = Dd / 64;   // 32
  for (int it = 0; it < NIT; ++it) {
    __syncthreads();
    if (it + 1 < NIT) load_stage(it + 1, (it + 1) & 1);
    else cp_commit();
    cp_wait1();
    __syncthreads();

    const __half* AQs = fs + (size_t)(it & 1) * (QK_STAGE / 2);
    const __half* AKs = AQs + 128 * ROWH;
    const __half* BQs = AQs + 256 * ROWH;
    const __half* BKs = BQs + 128 * ROWH;

    #pragma unroll
    for (int ks = 0; ks < 4; ++ks) {
      const int kc = ks * 16;
      uint32_t aQ[4][4], aK[4][4];
      #pragma unroll
      for (int i = 0; i < 4; ++i) {
        const int r = wm * 64 + i * 16 + g;
        aQ[i][0] = ldh2(AQs + (r    ) * ROWH + kc + 2 * tig);
        aQ[i][1] = ldh2(AQs + (r + 8) * ROWH + kc + 2 * tig);
        aQ[i][2] = ldh2(AQs + (r    ) * ROWH + kc + 2 * tig + 8);
        aQ[i][3] = ldh2(AQs + (r + 8) * ROWH + kc + 2 * tig + 8);
        aK[i][0] = ldh2(AKs + (r    ) * ROWH + kc + 2 * tig);
        aK[i][1] = ldh2(AKs + (r + 8) * ROWH + kc + 2 * tig);
        aK[i][2] = ldh2(AKs + (r    ) * ROWH + kc + 2 * tig + 8);
        aK[i][3] = ldh2(AKs + (r + 8) * ROWH + kc + 2 * tig + 8);
      }
      uint32_t bQ[4][2], bK[4][2];
      #pragma unroll
      for (int j = 0; j < 4; ++j) {
        const int n = wn * 32 + j * 8 + g;
        bQ[j][0] = ldh2(BQs + n * ROWH + kc + 2 * tig);
        bQ[j][1] = ldh2(BQs + n * ROWH + kc + 2 * tig + 8);
        bK[j][0] = ldh2(BKs + n * ROWH + kc + 2 * tig);
        bK[j][1] = ldh2(BKs + n * ROWH + kc + 2 * tig + 8);
      }
      #pragma unroll
      for (int i = 0; i < 4; ++i)
        #pragma unroll
        for (int j = 0; j < 4; ++j) {
          mma16(cQ[i][j], aQ[i], bQ[j]);
          mma16(cK[i][j], aK[i], bK[j]);
        }
    }
  }

  // Epilogue: bias + ELU + per-row reductions (sum Q, sum K, sum Q*K)
  float bqc[4][2], bkc[4][2];
  #pragma unroll
  for (int j = 0; j < 4; ++j) {
    const int col = n0 + wn * 32 + j * 8 + 2 * tig;
    bqc[j][0] = bq[col]; bqc[j][1] = bq[col + 1];
    bkc[j][0] = bk[col]; bkc[j][1] = bk[col + 1];
  }
  #pragma unroll
  for (int i = 0; i < 4; ++i) {
    const int r0 = m0 + wm * 64 + i * 16 + g;
    const int r1 = r0 + 8;
    float s0q = 0.f, s0k = 0.f, p0 = 0.f, s1q = 0.f, s1k = 0.f, p1 = 0.f;
    #pragma unroll
    for (int j = 0; j < 4; ++j) {
      float q00 = elu_f(cQ[i][j][0] + bqc[j][0]);
      float q01 = elu_f(cQ[i][j][1] + bqc[j][1]);
      float q10 = elu_f(cQ[i][j][2] + bqc[j][0]);
      float q11 = elu_f(cQ[i][j][3] + bqc[j][1]);
      float k00 = elu_f(cK[i][j][0] + bkc[j][0]);
      float k01 = elu_f(cK[i][j][1] + bkc[j][1]);
      float k10 = elu_f(cK[i][j][2] + bkc[j][0]);
      float k11 = elu_f(cK[i][j][3] + bkc[j][1]);
      s0q += q00 + q01; s0k += k00 + k01; p0 += q00 * k00 + q01 * k01;
      s1q += q10 + q11; s1k += k10 + k11; p1 += q10 * k10 + q11 * k11;
    }
    #pragma unroll
    for (int m = 1; m <= 2; m <<= 1) {
      s0q += __shfl_xor_sync(0xffffffffu, s0q, m);
      s0k += __shfl_xor_sync(0xffffffffu, s0k, m);
      p0  += __shfl_xor_sync(0xffffffffu, p0,  m);
      s1q += __shfl_xor_sync(0xffffffffu, s1q, m);
      s1k += __shfl_xor_sync(0xffffffffu, s1k, m);
      p1  += __shfl_xor_sync(0xffffffffu, p1,  m);
    }
    if (tig == 0) {
      atomicAdd(&g_sQ[r0], s0q); atomicAdd(&g_sK[r0], s0k); atomicAdd(&g_qk[r0], p0);
      atomicAdd(&g_sQ[r1], s1q); atomicAdd(&g_sK[r1], s1k); atomicAdd(&g_qk[r1], p1);
    }
  }
}

// ---------------- V projection kernel ----------------
// CTA 256 rows x 128 cols; 8 warps (wm 4 x wn 2), warp tile 64x64
// (acc 128 regs). K-chunk 64, 2-stage, 1 CTA/SM.
// Stage: A 256 rows = 36864 B, B 128 rows = 18432 B. Stage = 55296 B.
static constexpr int V_AREG  = 256 * ROWB;                // 36864
static constexpr int V_STAGE = V_AREG + 128 * ROWB;       // 55296
static constexpr int V_SMEM  = 2 * V_STAGE;               // 110592

__global__ void __launch_bounds__(256, 1)
gemm_v_kernel(const float* __restrict__ bv, float* __restrict__ out)
{
  extern __shared__ __align__(128) char smem[];
  __half* fs = reinterpret_cast<__half*>(smem);
  const uint32_t sb = smem_u32(smem);
  const int tid = threadIdx.x;
  const int wid = tid >> 5, lane = tid & 31;
  const int g = lane >> 2, tig = lane & 3;
  const int wm = wid >> 1, wn = wid & 1;
  const int m0 = blockIdx.y * 256;
  const int n0 = blockIdx.x * 128;

  auto load_stage = [&](int it, int s) {
    const int k0 = it * 64;
    const uint32_t base = sb + (uint32_t)s * V_STAGE;
    // A: 2048 chunks (256 rows), 8 per thread
    #pragma unroll
    for (int i = 0; i < 8; ++i) {
      int ch = tid + i * 256;
      int r = ch >> 3, c = ch & 7;
      cp16(base + (uint32_t)(r * ROWB + c * 16),
           g_Vh + (size_t)(m0 + r) * Dd + k0 + c * 8);
    }
    // B: 1024 chunks (128 rows), 4 per thread
    #pragma unroll
    for (int i = 0; i < 4; ++i) {
      int ch = tid + i * 256;
      int r = ch >> 3, c = ch & 7;
      cp16(base + (uint32_t)(V_AREG + r * ROWB + c * 16),
           g_WvT + (size_t)(n0 + r) * Dd + k0 + c * 8);
    }
    cp_commit();
  };

  float cc[4][8][4];
  #pragma unroll
  for (int i = 0; i < 4; ++i)
    #pragma unroll
    for (int j = 0; j < 8; ++j)
      #pragma unroll
      for (int t = 0; t < 4; ++t) cc[i][j][t] = 0.f;

  load_stage(0, 0);

  const int NIT = Dd / 64;   // 32
  for (int it = 0; it < NIT; ++it) {
    __syncthreads();
    if (it + 1 < NIT) load_stage(it + 1, (it + 1) & 1);
    else cp_commit();
    cp_wait1();
    __syncthreads();

    const __half* As = fs + (size_t)(it & 1) * (V_STAGE / 2);
    const __half* Bs = As + 256 * ROWH;       // = V_AREG in halves

    #pragma unroll
    for (int ks = 0; ks < 4; ++ks) {
      const int kc = ks * 16;
      uint32_t a[4][4];
      #pragma unroll
      for (int i = 0; i < 4; ++i) {
        const int r = wm * 64 + i * 16 + g;
        a[i][0] = ldh2(As + (r    ) * ROWH + kc + 2 * tig);
        a[i][1] = ldh2(As + (r + 8) * ROWH + kc + 2 * tig);
        a[i][2] = ldh2(As + (r    ) * ROWH + kc + 2 * tig + 8);
        a[i][3] = ldh2(As + (r + 8) * ROWH + kc + 2 * tig + 8);
      }
      uint32_t b[8][2];
      #pragma unroll
      for (int j = 0; j < 8; ++j) {
        const int n = wn * 64 + j * 8 + g;
        b[j][0] = ldh2(Bs + n * ROWH + kc + 2 * tig);
        b[j][1] = ldh2(Bs + n * ROWH + kc + 2 * tig + 8);
      }
      #pragma unroll
      for (int i = 0; i < 4; ++i)
        #pragma unroll
        for (int j = 0; j < 8; ++j)
          mma16(cc[i][j], a[i], b[j]);
    }
  }

  // Epilogue: out[r, n] = coef[r] * (acc + bv[n])
  float bvc[8][2];
  #pragma unroll
  for (int j = 0; j < 8; ++j) {
    const int col = n0 + wn * 64 + j * 8 + 2 * tig;
    bvc[j][0] = bv[col]; bvc[j][1] = bv[col + 1];
  }
  #pragma unroll
  for (int i = 0; i < 4; ++i) {
    const int r0 = m0 + wm * 64 + i * 16 + g;
    const int r1 = r0 + 8;
    const float c0 = g_qk[r0] / (g_sQ[r0] * g_sK[r0] + 1e-6f);
    const float c1 = g_qk[r1] / (g_sQ[r1] * g_sK[r1] + 1e-6f);
    #pragma unroll
    for (int j = 0; j < 8; ++j) {
      const int col = n0 + wn * 64 + j * 8 + 2 * tig;
      float2 v0, v1;
      v0.x = c0 * (cc[i][j][0] + bvc[j][0]);
      v0.y = c0 * (cc[i][j][1] + bvc[j][1]);
      v1.x = c1 * (cc[i][j][2] + bvc[j][0]);
      v1.y = c1 * (cc[i][j][3] + bvc[j][1]);
      *reinterpret_cast<float2*>(out + (size_t)r0 * Dd + col) = v0;
      *reinterpret_cast<float2*>(out + (size_t)r1 * Dd + col) = v1;
    }
  }
}

// ---------------- host launcher ----------------
extern "C" void kernel_launch(void* const* d_in, const int* /*in_sizes*/, int /*n_in*/,
                              void* d_out, int /*out_size*/) {
  const float* Q  = (const float*)d_in[0];
  const float* K  = (const float*)d_in[1];
  const float* V  = (const float*)d_in[2];
  const float* Wq = (const float*)d_in[3];
  const float* bq = (const float*)d_in[4];
  const float* Wk = (const float*)d_in[5];
  const float* bk = (const float*)d_in[6];
  const float* Wv = (const float*)d_in[7];
  const float* bv = (const float*)d_in[8];
  float* out = (float*)d_out;

  cudaFuncSetAttribute(gemm_qk_kernel, cudaFuncAttributeMaxDynamicSharedMemorySize, QK_SMEM);
  cudaFuncSetAttribute(gemm_v_kernel,  cudaFuncAttributeMaxDynamicSharedMemorySize, V_SMEM);

  // index 3 (the launch ncu profiles) = gemm_qk
  f2h_all_kernel<<<3 * 8192, 256>>>(Q, K, V);                                    // 0
  transpose_all_kernel<<<dim3(Dd / 32, Dd / 32, 3), dim3(32, 8)>>>(Wq, Wk, Wv);  // 1
  zero_kernel<<<Bn / 256, 256>>>();                                              // 2
  gemm_qk_kernel<<<dim3(Ff / 128, Bn / 128), 256, QK_SMEM>>>(bq, bk);            // 3
  gemm_v_kernel <<<dim3(Dd / 128, Bn / 256), 256, V_SMEM>>>(bv, out);            // 4
}

// round 9
// speedup vs baseline: 1.1965x; 1.1965x over previous
#include <cuda_runtime.h>
#include <cuda_fp16.h>
#include <cstdint>
#include <cstddef>

#define DEV __device__ __forceinline__

static constexpr int Bn = 8192;   // batch rows
static constexpr int Dd = 2048;   // model dim (K of GEMMs, N of V GEMM)
static constexpr int Ff = 1024;   // feature dim (N of Q/K GEMMs)

// ---------------- scratch (device globals: allocation-free) ----------------
__device__ __half g_Qh [(size_t)Bn * Dd];   // 32 MB
__device__ __half g_Kh [(size_t)Bn * Dd];   // 32 MB
__device__ __half g_Vh [(size_t)Bn * Dd];   // 32 MB
__device__ __half g_WqT[(size_t)Ff * Dd];   // [F][D] 4 MB
__device__ __half g_WkT[(size_t)Ff * Dd];   // [F][D] 4 MB
__device__ __half g_WvT[(size_t)Dd * Dd];   // [D][D] 8 MB
__device__ float g_sQ[Bn];
__device__ float g_sK[Bn];
__device__ float g_qk[Bn];

// ---------------- helpers ----------------
DEV uint32_t smem_u32(const void* p) {
  uint32_t a;
  asm("{ .reg .u64 t; cvta.to.shared.u64 t, %1; cvt.u32.u64 %0, t; }" : "=r"(a) : "l"(p));
  return a;
}
DEV void cp16(uint32_t dst, const void* src) {
  asm volatile("cp.async.cg.shared.global [%0], [%1], 16;" :: "r"(dst), "l"(src));
}
DEV void cp_commit() { asm volatile("cp.async.commit_group;" ::: "memory"); }
DEV void cp_wait1()  { asm volatile("cp.async.wait_group 1;" ::: "memory"); }
DEV void cp_wait2()  { asm volatile("cp.async.wait_group 2;" ::: "memory"); }

// mma m16n8k16 fp16 (fp32 acc)
DEV void mma16(float c[4], const uint32_t a[4], const uint32_t b[2]) {
  asm volatile(
    "mma.sync.aligned.m16n8k16.row.col.f32.f16.f16.f32 "
    "{%0,%1,%2,%3}, {%4,%5,%6,%7}, {%8,%9}, {%0,%1,%2,%3};"
    : "+f"(c[0]), "+f"(c[1]), "+f"(c[2]), "+f"(c[3])
    : "r"(a[0]), "r"(a[1]), "r"(a[2]), "r"(a[3]), "r"(b[0]), "r"(b[1]));
}

// ldmatrix x4: 4 consecutive 8x8 b16 matrices -> r[0..3]
DEV void ldsm4(uint32_t* r, uint32_t addr) {
  asm volatile("ldmatrix.sync.aligned.m8n8.x4.shared.b16 {%0,%1,%2,%3}, [%4];"
               : "=r"(r[0]), "=r"(r[1]), "=r"(r[2]), "=r"(r[3]) : "r"(addr));
}

DEV float elu_f(float x) { return x > 0.f ? x : expm1f(x); }
DEV uint32_t f2h2(float x, float y) {
  __half2 h = __floats2half2_rn(x, y);
  return *reinterpret_cast<uint32_t*>(&h);
}

// Smem rows: 64 k-halves (128 B data) padded to 72 halves (144 B = 9*16 B).
// ldmatrix phase (8 consecutive rows, one 16B seg each): banks 4i..4i+3,
// i = 0..7 -> all 32 banks exactly once: conflict-free.
static constexpr int ROWH = 72;                    // halves per padded row
static constexpr int ROWB = 144;                   // bytes per padded row

// ---------------- prep kernels ----------------
__global__ void f2h_all_kernel(const float* __restrict__ Q,
                               const float* __restrict__ K,
                               const float* __restrict__ V) {
  const int bi = blockIdx.x;            // 0..24575 (8192 blocks per tensor)
  const int which = bi >> 13;
  const int blk = bi & 8191;
  const float* src = (which == 0) ? Q : (which == 1) ? K : V;
  __half* dst = (which == 0) ? g_Qh : (which == 1) ? g_Kh : g_Vh;
  const size_t base = ((size_t)blk * 256 + threadIdx.x) * 8;
  float4 a = *reinterpret_cast<const float4*>(src + base);
  float4 b = *reinterpret_cast<const float4*>(src + base + 4);
  uint4 o;
  o.x = f2h2(a.x, a.y); o.y = f2h2(a.z, a.w);
  o.z = f2h2(b.x, b.y); o.w = f2h2(b.z, b.w);
  *reinterpret_cast<uint4*>(dst + base) = o;
}

__global__ void transpose_all_kernel(const float* __restrict__ Wq,
                                     const float* __restrict__ Wk,
                                     const float* __restrict__ Wv) {
  __shared__ float tile[32][33];
  const int z = blockIdx.z;
  // fold the reduction-buffer zeroing into the z==2 plane (64x64 blocks)
  if (z == 2) {
    int id = (blockIdx.y * 64 + blockIdx.x) * 256 + threadIdx.y * 32 + threadIdx.x;
    if (id < Bn) { g_sQ[id] = 0.f; g_sK[id] = 0.f; g_qk[id] = 0.f; }
  }
  if (z < 2 && blockIdx.x >= Ff / 32) return;
  const float* src = (z == 0) ? Wq : (z == 1) ? Wk : Wv;
  __half* dst = (z == 0) ? g_WqT : (z == 1) ? g_WkT : g_WvT;
  const int C = (z == 2) ? Dd : Ff;
  const int c0 = blockIdx.x * 32, r0 = blockIdx.y * 32;
  const int tx = threadIdx.x, ty = threadIdx.y;
  #pragma unroll
  for (int i = 0; i < 32; i += 8)
    tile[ty + i][tx] = src[(size_t)(r0 + ty + i) * C + (c0 + tx)];
  __syncthreads();
  #pragma unroll
  for (int i = 0; i < 32; i += 8)
    dst[(size_t)(c0 + ty + i) * Dd + (r0 + tx)] = __float2half_rn(tile[tx][ty + i]);
}

// ---------------- fused Q/K feature kernel ----------------
// CTA 64 rows x 128 feature cols, BOTH gemms; 8 warps (wm 2 x wn 4),
// warp tile 32x32 per gemm. K-chunk 64, 2-stage cp.async, 2 CTAs/SM.
// Stage: A region 128 rows (AQ 64 | AK 64), B region 256 rows (BQ 128 | BK 128).
static constexpr int QK_STAGE = (128 + 256) * ROWB;       // 55296
static constexpr int QK_SMEM  = 2 * QK_STAGE;             // 110592

__global__ void __launch_bounds__(256, 2)
gemm_qk_kernel(const float* __restrict__ bq, const float* __restrict__ bk)
{
  extern __shared__ __align__(128) char smem[];
  const uint32_t sb = smem_u32(smem);
  const int tid = threadIdx.x;
  const int wid = tid >> 5, lane = tid & 31;
  const int g = lane >> 2, tig = lane & 3;
  const int wm = wid >> 2, wn = wid & 3;
  const int m0 = blockIdx.y * 64;
  const int n0 = blockIdx.x * 128;

  auto load_stage = [&](int it, int s) {
    const int k0 = it * 64;                 // halves
    const uint32_t base = sb + (uint32_t)s * QK_STAGE;
    #pragma unroll
    for (int i = 0; i < 4; ++i) {           // A: 1024 chunks (Q rows 0-63, K 64-127)
      int ch = tid + i * 256;
      int r = ch >> 3, c = ch & 7;
      uint32_t off = (uint32_t)(r * ROWB + c * 16);
      const __half* src = (i < 2) ? (g_Qh + (size_t)(m0 + r) * Dd)
                                  : (g_Kh + (size_t)(m0 + r - 64) * Dd);
      cp16(base + off, src + k0 + c * 8);
    }
    #pragma unroll
    for (int i = 0; i < 8; ++i) {           // B: 2048 chunks (BQ 0-127, BK 128-255)
      int ch = tid + i * 256;
      int r = ch >> 3, c = ch & 7;
      uint32_t off = (uint32_t)(128 * ROWB + r * ROWB + c * 16);
      const __half* src = (i < 4) ? (g_WqT + (size_t)(n0 + r) * Dd)
                                  : (g_WkT + (size_t)(n0 + r - 128) * Dd);
      cp16(base + off, src + k0 + c * 8);
    }
    cp_commit();
  };

  // ldmatrix lane offsets (bytes within tile regions)
  const int l15 = lane & 15;
  const uint32_t aLane = (uint32_t)(l15 * ROWB) + ((lane >> 4) * 16);
  uint32_t aoff[2];
  #pragma unroll
  for (int i = 0; i < 2; ++i)
    aoff[i] = (uint32_t)((wm * 32 + i * 16) * ROWB) + aLane;
  const int nbl = ((lane >> 4) & 1) * 8 + (lane & 7);
  const uint32_t bLane = (uint32_t)(nbl * ROWB) + (((lane >> 3) & 1) * 16);
  uint32_t boff[2];
  #pragma unroll
  for (int jp = 0; jp < 2; ++jp)
    boff[jp] = (uint32_t)((wn * 32 + jp * 16) * ROWB) + bLane;

  float cQ[2][4][4], cK[2][4][4];
  #pragma unroll
  for (int i = 0; i < 2; ++i)
    #pragma unroll
    for (int j = 0; j < 4; ++j)
      #pragma unroll
      for (int t = 0; t < 4; ++t) { cQ[i][j][t] = 0.f; cK[i][j][t] = 0.f; }

  load_stage(0, 0);

  const int NIT = Dd / 64;   // 32
  for (int it = 0; it < NIT; ++it) {
    __syncthreads();
    if (it + 1 < NIT) load_stage(it + 1, (it + 1) & 1);
    else cp_commit();
    cp_wait1();
    __syncthreads();

    const uint32_t stA = sb + (uint32_t)(it & 1) * QK_STAGE;

    #pragma unroll
    for (int ks = 0; ks < 4; ++ks) {
      const uint32_t kb = ks * 32;          // 16 halves = 32 bytes
      uint32_t aQ[2][4], aK[2][4];
      ldsm4(aQ[0], stA + aoff[0] + kb);
      ldsm4(aQ[1], stA + aoff[1] + kb);
      ldsm4(aK[0], stA + 64 * ROWB + aoff[0] + kb);
      ldsm4(aK[1], stA + 64 * ROWB + aoff[1] + kb);
      uint32_t bQ[4][2], bK[4][2];
      ldsm4(&bQ[0][0], stA + 128 * ROWB + boff[0] + kb);
      ldsm4(&bQ[2][0], stA + 128 * ROWB + boff[1] + kb);
      ldsm4(&bK[0][0], stA + 256 * ROWB + boff[0] + kb);
      ldsm4(&bK[2][0], stA + 256 * ROWB + boff[1] + kb);
      #pragma unroll
      for (int i = 0; i < 2; ++i)
        #pragma unroll
        for (int j = 0; j < 4; ++j) {
          mma16(cQ[i][j], aQ[i], bQ[j]);
          mma16(cK[i][j], aK[i], bK[j]);
        }
    }
  }

  // Epilogue: bias + ELU + per-row reductions (sum Q, sum K, sum Q*K)
  float bqc[4][2], bkc[4][2];
  #pragma unroll
  for (int j = 0; j < 4; ++j) {
    const int col = n0 + wn * 32 + j * 8 + 2 * tig;
    bqc[j][0] = bq[col]; bqc[j][1] = bq[col + 1];
    bkc[j][0] = bk[col]; bkc[j][1] = bk[col + 1];
  }
  #pragma unroll
  for (int i = 0; i < 2; ++i) {
    const int r0 = m0 + wm * 32 + i * 16 + g;
    const int r1 = r0 + 8;
    float s0q = 0.f, s0k = 0.f, p0 = 0.f, s1q = 0.f, s1k = 0.f, p1 = 0.f;
    #pragma unroll
    for (int j = 0; j < 4; ++j) {
      float q00 = elu_f(cQ[i][j][0] + bqc[j][0]);
      float q01 = elu_f(cQ[i][j][1] + bqc[j][1]);
      float q10 = elu_f(cQ[i][j][2] + bqc[j][0]);
      float q11 = elu_f(cQ[i][j][3] + bqc[j][1]);
      float k00 = elu_f(cK[i][j][0] + bkc[j][0]);
      float k01 = elu_f(cK[i][j][1] + bkc[j][1]);
      float k10 = elu_f(cK[i][j][2] + bkc[j][0]);
      float k11 = elu_f(cK[i][j][3] + bkc[j][1]);
      s0q += q00 + q01; s0k += k00 + k01; p0 += q00 * k00 + q01 * k01;
      s1q += q10 + q11; s1k += k10 + k11; p1 += q10 * k10 + q11 * k11;
    }
    #pragma unroll
    for (int m = 1; m <= 2; m <<= 1) {
      s0q += __shfl_xor_sync(0xffffffffu, s0q, m);
      s0k += __shfl_xor_sync(0xffffffffu, s0k, m);
      p0  += __shfl_xor_sync(0xffffffffu, p0,  m);
      s1q += __shfl_xor_sync(0xffffffffu, s1q, m);
      s1k += __shfl_xor_sync(0xffffffffu, s1k, m);
      p1  += __shfl_xor_sync(0xffffffffu, p1,  m);
    }
    if (tig == 0) {
      atomicAdd(&g_sQ[r0], s0q); atomicAdd(&g_sK[r0], s0k); atomicAdd(&g_qk[r0], p0);
      atomicAdd(&g_sQ[r1], s1q); atomicAdd(&g_sK[r1], s1k); atomicAdd(&g_qk[r1], p1);
    }
  }
}

// ---------------- V projection kernel ----------------
// CTA 128x128, warp tile 64x32, K-chunk 64, 3-stage pipeline, 2 CTAs/SM.
static constexpr int TILE_B  = 128 * ROWB;                // 18432
static constexpr int V_STAGE = 2 * TILE_B;                // 36864
static constexpr int V_SMEM  = 3 * V_STAGE;               // 110592

__global__ void __launch_bounds__(256, 2)
gemm_v_kernel(const float* __restrict__ bv, float* __restrict__ out)
{
  extern __shared__ __align__(128) char smem[];
  const uint32_t sb = smem_u32(smem);
  const int tid = threadIdx.x;
  const int wid = tid >> 5, lane = tid & 31;
  const int g = lane >> 2, tig = lane & 3;
  const int wm = wid >> 2, wn = wid & 3;
  const int m0 = blockIdx.y * 128;
  const int n0 = blockIdx.x * 128;

  auto load_stage = [&](int it, int s) {
    const int k0 = it * 64;
    const uint32_t base = sb + (uint32_t)s * V_STAGE;
    #pragma unroll
    for (int i = 0; i < 4; ++i) {
      int ch = tid + i * 256;
      int r = ch >> 3, c = ch & 7;
      uint32_t off = (uint32_t)(r * ROWB + c * 16);
      cp16(base + off,          g_Vh  + (size_t)(m0 + r) * Dd + k0 + c * 8);
      cp16(base + TILE_B + off, g_WvT + (size_t)(n0 + r) * Dd + k0 + c * 8);
    }
    cp_commit();
  };

  // ldmatrix lane offsets
  const int l15 = lane & 15;
  const uint32_t aLane = (uint32_t)(l15 * ROWB) + ((lane >> 4) * 16);
  uint32_t aoff[4];
  #pragma unroll
  for (int i = 0; i < 4; ++i)
    aoff[i] = (uint32_t)((wm * 64 + i * 16) * ROWB) + aLane;
  const int nbl = ((lane >> 4) & 1) * 8 + (lane & 7);
  const uint32_t bLane = (uint32_t)(nbl * ROWB) + (((lane >> 3) & 1) * 16);
  uint32_t boff[2];
  #pragma unroll
  for (int jp = 0; jp < 2; ++jp)
    boff[jp] = (uint32_t)((wn * 32 + jp * 16) * ROWB) + bLane;

  float cc[4][4][4];
  #pragma unroll
  for (int i = 0; i < 4; ++i)
    #pragma unroll
    for (int j = 0; j < 4; ++j)
      #pragma unroll
      for (int t = 0; t < 4; ++t) cc[i][j][t] = 0.f;

  load_stage(0, 0);
  load_stage(1, 1);

  const int NIT = Dd / 64;   // 32
  for (int it = 0; it < NIT; ++it) {
    __syncthreads();
    if (it + 2 < NIT) load_stage(it + 2, (it + 2) % 3);
    else cp_commit();
    cp_wait2();
    __syncthreads();

    const uint32_t stA = sb + (uint32_t)(it % 3) * V_STAGE;

    #pragma unroll
    for (int ks = 0; ks < 4; ++ks) {
      const uint32_t kb = ks * 32;
      uint32_t a[4][4];
      ldsm4(a[0], stA + aoff[0] + kb);
      ldsm4(a[1], stA + aoff[1] + kb);
      ldsm4(a[2], stA + aoff[2] + kb);
      ldsm4(a[3], stA + aoff[3] + kb);
      uint32_t b[4][2];
      ldsm4(&b[0][0], stA + TILE_B + boff[0] + kb);
      ldsm4(&b[2][0], stA + TILE_B + boff[1] + kb);
      #pragma unroll
      for (int i = 0; i < 4; ++i)
        #pragma unroll
        for (int j = 0; j < 4; ++j)
          mma16(cc[i][j], a[i], b[j]);
    }
  }

  // Epilogue: out[r, n] = coef[r] * (acc + bv[n])
  float bvc[4][2];
  #pragma unroll
  for (int j = 0; j < 4; ++j) {
    const int col = n0 + wn * 32 + j * 8 + 2 * tig;
    bvc[j][0] = bv[col]; bvc[j][1] = bv[col + 1];
  }
  #pragma unroll
  for (int i = 0; i < 4; ++i) {
    const int r0 = m0 + wm * 64 + i * 16 + g;
    const int r1 = r0 + 8;
    const float c0 = g_qk[r0] / (g_sQ[r0] * g_sK[r0] + 1e-6f);
    const float c1 = g_qk[r1] / (g_sQ[r1] * g_sK[r1] + 1e-6f);
    #pragma unroll
    for (int j = 0; j < 4; ++j) {
      const int col = n0 + wn * 32 + j * 8 + 2 * tig;
      float2 v0, v1;
      v0.x = c0 * (cc[i][j][0] + bvc[j][0]);
      v0.y = c0 * (cc[i][j][1] + bvc[j][1]);
      v1.x = c1 * (cc[i][j][2] + bvc[j][0]);
      v1.y = c1 * (cc[i][j][3] + bvc[j][1]);
      *reinterpret_cast<float2*>(out + (size_t)r0 * Dd + col) = v0;
      *reinterpret_cast<float2*>(out + (size_t)r1 * Dd + col) = v1;
    }
  }
}

// ---------------- host launcher ----------------
extern "C" void kernel_launch(void* const* d_in, const int* /*in_sizes*/, int /*n_in*/,
                              void* d_out, int /*out_size*/) {
  const float* Q  = (const float*)d_in[0];
  const float* K  = (const float*)d_in[1];
  const float* V  = (const float*)d_in[2];
  const float* Wq = (const float*)d_in[3];
  const float* bq = (const float*)d_in[4];
  const float* Wk = (const float*)d_in[5];
  const float* bk = (const float*)d_in[6];
  const float* Wv = (const float*)d_in[7];
  const float* bv = (const float*)d_in[8];
  float* out = (float*)d_out;

  cudaFuncSetAttribute(gemm_qk_kernel, cudaFuncAttributeMaxDynamicSharedMemorySize, QK_SMEM);
  cudaFuncSetAttribute(gemm_v_kernel,  cudaFuncAttributeMaxDynamicSharedMemorySize, V_SMEM);

  // launch index 3 (the one ncu profiles) = gemm_v this time
  f2h_all_kernel<<<3 * 8192, 256>>>(Q, K, V);                                    // 0
  transpose_all_kernel<<<dim3(Dd / 32, Dd / 32, 3), dim3(32, 8)>>>(Wq, Wk, Wv);  // 1 (+zeroing)
  gemm_qk_kernel<<<dim3(Ff / 128, Bn / 64), 256, QK_SMEM>>>(bq, bk);             // 2
  gemm_v_kernel <<<dim3(Dd / 128, Bn / 128), 256, V_SMEM>>>(bv, out);            // 3
}

// round 10
// speedup vs baseline: 1.2167x; 1.0169x over previous
#include <cuda_runtime.h>
#include <cuda_fp16.h>
#include <cstdint>
#include <cstddef>

#define DEV __device__ __forceinline__

static constexpr int Bn = 8192;   // batch rows
static constexpr int Dd = 2048;   // model dim (K of GEMMs, N of V GEMM)
static constexpr int Ff = 1024;   // feature dim (N of Q/K GEMMs)

// ---------------- scratch (device globals: allocation-free) ----------------
__device__ __half g_Qh [(size_t)Bn * Dd];   // 32 MB
__device__ __half g_Kh [(size_t)Bn * Dd];   // 32 MB
__device__ __half g_Vh [(size_t)Bn * Dd];   // 32 MB
__device__ __half g_WqT[(size_t)Ff * Dd];   // [F][D] 4 MB
__device__ __half g_WkT[(size_t)Ff * Dd];   // [F][D] 4 MB
__device__ __half g_WvT[(size_t)Dd * Dd];   // [D][D] 8 MB
__device__ float g_sQ[Bn];
__device__ float g_sK[Bn];
__device__ float g_qk[Bn];

// ---------------- helpers ----------------
DEV uint32_t smem_u32(const void* p) {
  uint32_t a;
  asm("{ .reg .u64 t; cvta.to.shared.u64 t, %1; cvt.u32.u64 %0, t; }" : "=r"(a) : "l"(p));
  return a;
}
DEV void cp16(uint32_t dst, const void* src) {
  asm volatile("cp.async.cg.shared.global [%0], [%1], 16;" :: "r"(dst), "l"(src));
}
DEV void cp_commit() { asm volatile("cp.async.commit_group;" ::: "memory"); }
DEV void cp_wait0()  { asm volatile("cp.async.wait_group 0;" ::: "memory"); }
DEV void cp_wait1()  { asm volatile("cp.async.wait_group 1;" ::: "memory"); }

// mma m16n8k16 fp16 (fp32 acc)
DEV void mma16(float c[4], const uint32_t a[4], const uint32_t b[2]) {
  asm volatile(
    "mma.sync.aligned.m16n8k16.row.col.f32.f16.f16.f32 "
    "{%0,%1,%2,%3}, {%4,%5,%6,%7}, {%8,%9}, {%0,%1,%2,%3};"
    : "+f"(c[0]), "+f"(c[1]), "+f"(c[2]), "+f"(c[3])
    : "r"(a[0]), "r"(a[1]), "r"(a[2]), "r"(a[3]), "r"(b[0]), "r"(b[1]));
}

// ldmatrix x4: 4 consecutive 8x8 b16 matrices -> r[0..3]
DEV void ldsm4(uint32_t* r, uint32_t addr) {
  asm volatile("ldmatrix.sync.aligned.m8n8.x4.shared.b16 {%0,%1,%2,%3}, [%4];"
               : "=r"(r[0]), "=r"(r[1]), "=r"(r[2]), "=r"(r[3]) : "r"(addr));
}

DEV float elu_f(float x) { return x > 0.f ? x : expm1f(x); }
DEV uint32_t f2h2(float x, float y) {
  __half2 h = __floats2half2_rn(x, y);
  return *reinterpret_cast<uint32_t*>(&h);
}

// Smem rows: 64 k-halves (128 B data) padded to 72 halves (144 B = 9*16 B).
// ldmatrix phase (8 consecutive rows, one 16B seg each): banks 4i..4i+3 -> all
// 32 banks once: conflict-free.
static constexpr int ROWH = 72;                    // halves per padded row
static constexpr int ROWB = 144;                   // bytes per padded row

// QK epilogue staging: 64 rows x 128 cols fp32, rows padded to 136 floats
// (bank = (8g + 2tig + c) mod 32 -> distinct across warp: conflict-free).
static constexpr int EPIW = 136;

// ---------------- prep kernels ----------------
__global__ void f2h_all_kernel(const float* __restrict__ Q,
                               const float* __restrict__ K,
                               const float* __restrict__ V) {
  const int bi = blockIdx.x;            // 0..24575 (8192 blocks per tensor)
  const int which = bi >> 13;
  const int blk = bi & 8191;
  const float* src = (which == 0) ? Q : (which == 1) ? K : V;
  __half* dst = (which == 0) ? g_Qh : (which == 1) ? g_Kh : g_Vh;
  const size_t base = ((size_t)blk * 256 + threadIdx.x) * 8;
  float4 a = *reinterpret_cast<const float4*>(src + base);
  float4 b = *reinterpret_cast<const float4*>(src + base + 4);
  uint4 o;
  o.x = f2h2(a.x, a.y); o.y = f2h2(a.z, a.w);
  o.z = f2h2(b.x, b.y); o.w = f2h2(b.z, b.w);
  *reinterpret_cast<uint4*>(dst + base) = o;
}

__global__ void transpose_qk_kernel(const float* __restrict__ Wq,
                                    const float* __restrict__ Wk) {
  __shared__ float tile[32][33];
  const float* src = (blockIdx.z == 0) ? Wq : Wk;
  __half* dst = (blockIdx.z == 0) ? g_WqT : g_WkT;
  const int c0 = blockIdx.x * 32, r0 = blockIdx.y * 32;
  const int tx = threadIdx.x, ty = threadIdx.y;
  #pragma unroll
  for (int i = 0; i < 32; i += 8)
    tile[ty + i][tx] = src[(size_t)(r0 + ty + i) * Ff + (c0 + tx)];
  __syncthreads();
  #pragma unroll
  for (int i = 0; i < 32; i += 8)
    dst[(size_t)(c0 + ty + i) * Dd + (r0 + tx)] = __float2half_rn(tile[tx][ty + i]);
}

__global__ void transpose_v_kernel(const float* __restrict__ Wv) {
  __shared__ float tile[32][33];
  // fold reduction-buffer zeroing in
  int id = (blockIdx.y * 64 + blockIdx.x) * 256 + threadIdx.y * 32 + threadIdx.x;
  if (id < Bn) { g_sQ[id] = 0.f; g_sK[id] = 0.f; g_qk[id] = 0.f; }
  const int c0 = blockIdx.x * 32, r0 = blockIdx.y * 32;
  const int tx = threadIdx.x, ty = threadIdx.y;
  #pragma unroll
  for (int i = 0; i < 32; i += 8)
    tile[ty + i][tx] = Wv[(size_t)(r0 + ty + i) * Dd + (c0 + tx)];
  __syncthreads();
  #pragma unroll
  for (int i = 0; i < 32; i += 8)
    g_WvT[(size_t)(c0 + ty + i) * Dd + (r0 + tx)] = __float2half_rn(tile[tx][ty + i]);
}

// ---------------- fused Q/K feature kernel ----------------
// CTA 64 rows x 128 cols. Warp split: warps 0-3 -> Q gemm, warps 4-7 -> K gemm;
// each warp tile 64x32 (acc 64 regs). K-chunk 64, 2-stage, single-barrier
// pipeline, 2 CTAs/SM. Stage: A 128 rows (Q 64 | K 64), B 256 rows (BQ | BK).
// Epilogue: per-side sums directly; q*k via smem staging of K tile.
static constexpr int QK_STAGE = (128 + 256) * ROWB;       // 55296
static constexpr int QK_SMEM  = 2 * QK_STAGE;             // 110592

__global__ void __launch_bounds__(256, 2)
gemm_qk_kernel(const float* __restrict__ bq, const float* __restrict__ bk)
{
  extern __shared__ __align__(128) char smem[];
  const uint32_t sb = smem_u32(smem);
  const int tid = threadIdx.x;
  const int wid = tid >> 5, lane = tid & 31;
  const int g = lane >> 2, tig = lane & 3;
  const int side = wid >> 2;          // 0 = Q gemm, 1 = K gemm
  const int w = wid & 3;              // 32-col block within 128
  const int m0 = blockIdx.y * 64;
  const int n0 = blockIdx.x * 128;

  auto load_stage = [&](int it, int s) {
    const int k0 = it * 64;                 // halves
    const uint32_t base = sb + (uint32_t)s * QK_STAGE;
    #pragma unroll
    for (int i = 0; i < 4; ++i) {           // A: 1024 chunks (Q rows 0-63, K 64-127)
      int ch = tid + i * 256;
      int r = ch >> 3, c = ch & 7;
      uint32_t off = (uint32_t)(r * ROWB + c * 16);
      const __half* src = (i < 2) ? (g_Qh + (size_t)(m0 + r) * Dd)
                                  : (g_Kh + (size_t)(m0 + r - 64) * Dd);
      cp16(base + off, src + k0 + c * 8);
    }
    #pragma unroll
    for (int i = 0; i < 8; ++i) {           // B: 2048 chunks (BQ 0-127, BK 128-255)
      int ch = tid + i * 256;
      int r = ch >> 3, c = ch & 7;
      uint32_t off = (uint32_t)(128 * ROWB + r * ROWB + c * 16);
      const __half* src = (i < 4) ? (g_WqT + (size_t)(n0 + r) * Dd)
                                  : (g_WkT + (size_t)(n0 + r - 128) * Dd);
      cp16(base + off, src + k0 + c * 8);
    }
    cp_commit();
  };

  // ldmatrix lane offsets
  const int l15 = lane & 15;
  const uint32_t aLane = (uint32_t)(l15 * ROWB) + ((lane >> 4) * 16);
  uint32_t aoff[4];
  #pragma unroll
  for (int i = 0; i < 4; ++i)
    aoff[i] = (uint32_t)((side * 64 + i * 16) * ROWB) + aLane;
  const int nbl = ((lane >> 4) & 1) * 8 + (lane & 7);
  const uint32_t bLane = (uint32_t)(nbl * ROWB) + (((lane >> 3) & 1) * 16);
  uint32_t boff[2];
  #pragma unroll
  for (int jp = 0; jp < 2; ++jp)
    boff[jp] = (uint32_t)((128 + side * 128 + w * 32 + jp * 16) * ROWB) + bLane;

  float cc[4][4][4];
  #pragma unroll
  for (int i = 0; i < 4; ++i)
    #pragma unroll
    for (int j = 0; j < 4; ++j)
      #pragma unroll
      for (int t = 0; t < 4; ++t) cc[i][j][t] = 0.f;

  load_stage(0, 0);

  const int NIT = Dd / 64;   // 32
  for (int it = 0; it < NIT; ++it) {
    cp_wait0();                // load(it) landed (issued one full iter earlier)
    __syncthreads();           // all warps done reading stage (it-1)&1
    if (it + 1 < NIT) load_stage(it + 1, (it + 1) & 1);

    const uint32_t stA = sb + (uint32_t)(it & 1) * QK_STAGE;
    #pragma unroll
    for (int ks = 0; ks < 4; ++ks) {
      const uint32_t kb = ks * 32;          // 16 halves = 32 bytes
      uint32_t a[4][4];
      ldsm4(a[0], stA + aoff[0] + kb);
      ldsm4(a[1], stA + aoff[1] + kb);
      ldsm4(a[2], stA + aoff[2] + kb);
      ldsm4(a[3], stA + aoff[3] + kb);
      uint32_t b[4][2];
      ldsm4(&b[0][0], stA + boff[0] + kb);
      ldsm4(&b[2][0], stA + boff[1] + kb);
      #pragma unroll
      for (int i = 0; i < 4; ++i)
        #pragma unroll
        for (int j = 0; j < 4; ++j)
          mma16(cc[i][j], a[i], b[j]);
    }
  }

  // ---- epilogue ----
  const float* bias = side ? bk : bq;
  float bb[4][2];
  #pragma unroll
  for (int j = 0; j < 4; ++j) {
    const int col = n0 + w * 32 + j * 8 + 2 * tig;
    bb[j][0] = bias[col]; bb[j][1] = bias[col + 1];
  }
  // bias + ELU in place; per-row own-side sums
  #pragma unroll
  for (int i = 0; i < 4; ++i) {
    float s0 = 0.f, s1 = 0.f;
    #pragma unroll
    for (int j = 0; j < 4; ++j) {
      cc[i][j][0] = elu_f(cc[i][j][0] + bb[j][0]);
      cc[i][j][1] = elu_f(cc[i][j][1] + bb[j][1]);
      cc[i][j][2] = elu_f(cc[i][j][2] + bb[j][0]);
      cc[i][j][3] = elu_f(cc[i][j][3] + bb[j][1]);
      s0 += cc[i][j][0] + cc[i][j][1];
      s1 += cc[i][j][2] + cc[i][j][3];
    }
    #pragma unroll
    for (int m = 1; m <= 2; m <<= 1) {
      s0 += __shfl_xor_sync(0xffffffffu, s0, m);
      s1 += __shfl_xor_sync(0xffffffffu, s1, m);
    }
    if (tig == 0) {
      float* arr = side ? g_sK : g_sQ;
      atomicAdd(&arr[m0 + i * 16 + g], s0);
      atomicAdd(&arr[m0 + i * 16 + g + 8], s1);
    }
  }
  __syncthreads();             // mainloop smem reads done everywhere
  float* epi = reinterpret_cast<float*>(smem);   // 64 x EPIW floats
  if (side == 1) {             // K warps stage their ELU'd tile
    #pragma unroll
    for (int i = 0; i < 4; ++i) {
      const int r0 = i * 16 + g, r1 = r0 + 8;
      #pragma unroll
      for (int j = 0; j < 4; ++j) {
        const int c = w * 32 + j * 8 + 2 * tig;
        *reinterpret_cast<float2*>(epi + r0 * EPIW + c) = make_float2(cc[i][j][0], cc[i][j][1]);
        *reinterpret_cast<float2*>(epi + r1 * EPIW + c) = make_float2(cc[i][j][2], cc[i][j][3]);
      }
    }
  }
  __syncthreads();
  if (side == 0) {             // Q warps form q*k row-products
    #pragma unroll
    for (int i = 0; i < 4; ++i) {
      const int r0 = i * 16 + g, r1 = r0 + 8;
      float p0 = 0.f, p1 = 0.f;
      #pragma unroll
      for (int j = 0; j < 4; ++j) {
        const int c = w * 32 + j * 8 + 2 * tig;
        float2 k0v = *reinterpret_cast<const float2*>(epi + r0 * EPIW + c);
        float2 k1v = *reinterpret_cast<const float2*>(epi + r1 * EPIW + c);
        p0 += cc[i][j][0] * k0v.x + cc[i][j][1] * k0v.y;
        p1 += cc[i][j][2] * k1v.x + cc[i][j][3] * k1v.y;
      }
      #pragma unroll
      for (int m = 1; m <= 2; m <<= 1) {
        p0 += __shfl_xor_sync(0xffffffffu, p0, m);
        p1 += __shfl_xor_sync(0xffffffffu, p1, m);
      }
      if (tig == 0) {
        atomicAdd(&g_qk[m0 + i * 16 + g], p0);
        atomicAdd(&g_qk[m0 + i * 16 + g + 8], p1);
      }
    }
  }
}

// ---------------- V projection kernel ----------------
// CTA 128x128, warp tile 64x32, K-chunk 64, 3-stage single-barrier pipeline,
// 2 CTAs/SM.
static constexpr int TILE_B  = 128 * ROWB;                // 18432
static constexpr int V_STAGE = 2 * TILE_B;                // 36864
static constexpr int V_SMEM  = 3 * V_STAGE;               // 110592

__global__ void __launch_bounds__(256, 2)
gemm_v_kernel(const float* __restrict__ bv, float* __restrict__ out)
{
  extern __shared__ __align__(128) char smem[];
  const uint32_t sb = smem_u32(smem);
  const int tid = threadIdx.x;
  const int wid = tid >> 5, lane = tid & 31;
  const int g = lane >> 2, tig = lane & 3;
  const int wm = wid >> 2, wn = wid & 3;
  const int m0 = blockIdx.y * 128;
  const int n0 = blockIdx.x * 128;

  auto load_stage = [&](int it, int s) {
    const int k0 = it * 64;
    const uint32_t base = sb + (uint32_t)s * V_STAGE;
    #pragma unroll
    for (int i = 0; i < 4; ++i) {
      int ch = tid + i * 256;
      int r = ch >> 3, c = ch & 7;
      uint32_t off = (uint32_t)(r * ROWB + c * 16);
      cp16(base + off,          g_Vh  + (size_t)(m0 + r) * Dd + k0 + c * 8);
      cp16(base + TILE_B + off, g_WvT + (size_t)(n0 + r) * Dd + k0 + c * 8);
    }
    cp_commit();
  };

  const int l15 = lane & 15;
  const uint32_t aLane = (uint32_t)(l15 * ROWB) + ((lane >> 4) * 16);
  uint32_t aoff[4];
  #pragma unroll
  for (int i = 0; i < 4; ++i)
    aoff[i] = (uint32_t)((wm * 64 + i * 16) * ROWB) + aLane;
  const int nbl = ((lane >> 4) & 1) * 8 + (lane & 7);
  const uint32_t bLane = (uint32_t)(nbl * ROWB) + (((lane >> 3) & 1) * 16);
  uint32_t boff[2];
  #pragma unroll
  for (int jp = 0; jp < 2; ++jp)
    boff[jp] = (uint32_t)((wn * 32 + jp * 16) * ROWB) + bLane;

  float cc[4][4][4];
  #pragma unroll
  for (int i = 0; i < 4; ++i)
    #pragma unroll
    for (int j = 0; j < 4; ++j)
      #pragma unroll
      for (int t = 0; t < 4; ++t) cc[i][j][t] = 0.f;

  load_stage(0, 0);
  load_stage(1, 1);

  const int NIT = Dd / 64;   // 32
  for (int it = 0; it < NIT; ++it) {
    cp_wait1();                // load(it) landed; load(it+1) may be in flight
    __syncthreads();           // all warps done reading stage (it-1)%3
    if (it + 2 < NIT) load_stage(it + 2, (it + 2) % 3);
    else cp_commit();          // keep group counts uniform for wait1

    const uint32_t stA = sb + (uint32_t)(it % 3) * V_STAGE;
    #pragma unroll
    for (int ks = 0; ks < 4; ++ks) {
      const uint32_t kb = ks * 32;
      uint32_t a[4][4];
      ldsm4(a[0], stA + aoff[0] + kb);
      ldsm4(a[1], stA + aoff[1] + kb);
      ldsm4(a[2], stA + aoff[2] + kb);
      ldsm4(a[3], stA + aoff[3] + kb);
      uint32_t b[4][2];
      ldsm4(&b[0][0], stA + TILE_B + boff[0] + kb);
      ldsm4(&b[2][0], stA + TILE_B + boff[1] + kb);
      #pragma unroll
      for (int i = 0; i < 4; ++i)
        #pragma unroll
        for (int j = 0; j < 4; ++j)
          mma16(cc[i][j], a[i], b[j]);
    }
  }

  // Epilogue: out[r, n] = coef[r] * (acc + bv[n])
  float bvc[4][2];
  #pragma unroll
  for (int j = 0; j < 4; ++j) {
    const int col = n0 + wn * 32 + j * 8 + 2 * tig;
    bvc[j][0] = bv[col]; bvc[j][1] = bv[col + 1];
  }
  #pragma unroll
  for (int i = 0; i < 4; ++i) {
    const int r0 = m0 + wm * 64 + i * 16 + g;
    const int r1 = r0 + 8;
    const float c0 = g_qk[r0] / (g_sQ[r0] * g_sK[r0] + 1e-6f);
    const float c1 = g_qk[r1] / (g_sQ[r1] * g_sK[r1] + 1e-6f);
    #pragma unroll
    for (int j = 0; j < 4; ++j) {
      const int col = n0 + wn * 32 + j * 8 + 2 * tig;
      float2 v0, v1;
      v0.x = c0 * (cc[i][j][0] + bvc[j][0]);
      v0.y = c0 * (cc[i][j][1] + bvc[j][1]);
      v1.x = c1 * (cc[i][j][2] + bvc[j][0]);
      v1.y = c1 * (cc[i][j][3] + bvc[j][1]);
      *reinterpret_cast<float2*>(out + (size_t)r0 * Dd + col) = v0;
      *reinterpret_cast<float2*>(out + (size_t)r1 * Dd + col) = v1;
    }
  }
}

// ---------------- host launcher ----------------
extern "C" void kernel_launch(void* const* d_in, const int* /*in_sizes*/, int /*n_in*/,
                              void* d_out, int /*out_size*/) {
  const float* Q  = (const float*)d_in[0];
  const float* K  = (const float*)d_in[1];
  const float* V  = (const float*)d_in[2];
  const float* Wq = (const float*)d_in[3];
  const float* bq = (const float*)d_in[4];
  const float* Wk = (const float*)d_in[5];
  const float* bk = (const float*)d_in[6];
  const float* Wv = (const float*)d_in[7];
  const float* bv = (const float*)d_in[8];
  float* out = (float*)d_out;

  cudaFuncSetAttribute(gemm_qk_kernel, cudaFuncAttributeMaxDynamicSharedMemorySize, QK_SMEM);
  cudaFuncSetAttribute(gemm_v_kernel,  cudaFuncAttributeMaxDynamicSharedMemorySize, V_SMEM);

  // launch index 3 (the one ncu profiles) = gemm_qk (restructured this round)
  f2h_all_kernel<<<3 * 8192, 256>>>(Q, K, V);                                    // 0
  transpose_qk_kernel<<<dim3(Ff / 32, Dd / 32, 2), dim3(32, 8)>>>(Wq, Wk);       // 1
  transpose_v_kernel <<<dim3(Dd / 32, Dd / 32),    dim3(32, 8)>>>(Wv);           // 2 (+zeroing)
  gemm_qk_kernel<<<dim3(Ff / 128, Bn / 64), 256, QK_SMEM>>>(bq, bk);             // 3
  gemm_v_kernel <<<dim3(Dd / 128, Bn / 128), 256, V_SMEM>>>(bv, out);            // 4
}